// round 16
// baseline (speedup 1.0000x reference)
#include <cuda_runtime.h>
#include <cuda_fp16.h>
#include <math.h>

// ---------------- problem constants ----------------
#define D_MODEL 512
#define HEADS   8
#define DK      64
#define N_LAYERS 4
#define BS      16
#define SEQ     4096
#define EPS     1e-6f
#define ROWS    (BS * SEQ)              // 65536
#define INV_SQRT_DK 0.125f
#define SCHUNKS 32
#define DD      (D_MODEL * D_MODEL)     // 262144

typedef unsigned long long ull;

// ---------------- scratch (device globals; device-code access ONLY) ----------
__device__ float  g_x [(size_t)ROWS * D_MODEL];   // z buffer (fp32)
__device__ __half g_yh[(size_t)ROWS * D_MODEL];   // norm1 out hi
__device__ __half g_yl[(size_t)ROWS * D_MODEL];   // norm1 out lo
__device__ float g_part[(size_t)BS * SCHUNKS * D_MODEL];
__device__ float g_ksum[BS * D_MODEL];
__device__ float g_M[(size_t)BS * HEADS * DK * DK];          // scores + I
// W~_b = Wo . blockdiag(S+I)   [16][512][512] hi/lo
__device__ __half g_Wth[(size_t)BS * DD];
__device__ __half g_Wtl[(size_t)BS * DD];
// composed per-batch weights W^_b = W~_b @ Wv   [16][512][512] hi/lo
__device__ __half g_What[(size_t)BS * DD];
__device__ __half g_Whal[(size_t)BS * DD];
// Wv transposed + split, all layers: WvT[L][d][k] = Wv[L][k][d]
__device__ __half g_WvTh[(size_t)N_LAYERS * DD];
__device__ __half g_WvTl[(size_t)N_LAYERS * DD];
// composed bias b^_b[o] = bo[o] + sum_k W~_b[o,k] bv[k]
__device__ float g_bhat[BS * D_MODEL];

// ---------------- helpers -----------------------------------------------------
__device__ __forceinline__ void hsplit(float v, __half& h, __half& l) {
    h = __float2half_rn(v);
    l = __float2half_rn(v - __half2float(h));
}
__device__ __forceinline__ unsigned hpack2(__half a, __half b) {
    __half2 p = __halves2half2(a, b);
    return *reinterpret_cast<unsigned*>(&p);
}
__device__ __forceinline__ uint2 hpack4(__half a, __half b, __half c, __half d) {
    uint2 u;
    u.x = hpack2(a, b);
    u.y = hpack2(c, d);
    return u;
}
__device__ __forceinline__ unsigned smem_u32(const void* p) {
    unsigned a;
    asm("{ .reg .u64 t; cvta.to.shared.u64 t, %1; cvt.u32.u64 %0, t; }"
        : "=r"(a) : "l"(p));
    return a;
}
__device__ __forceinline__ void mma16816(float* c, const unsigned* a, const unsigned* b) {
    asm volatile(
        "mma.sync.aligned.m16n8k16.row.col.f32.f16.f16.f32 "
        "{%0,%1,%2,%3}, {%4,%5,%6,%7}, {%8,%9}, {%0,%1,%2,%3};"
        : "+f"(c[0]), "+f"(c[1]), "+f"(c[2]), "+f"(c[3])
        : "r"(a[0]), "r"(a[1]), "r"(a[2]), "r"(a[3]), "r"(b[0]), "r"(b[1]));
}
__device__ __forceinline__ void ldsm4(unsigned* r, unsigned addr) {
    asm volatile("ldmatrix.sync.aligned.m8n8.x4.shared.b16 {%0,%1,%2,%3}, [%4];"
                 : "=r"(r[0]), "=r"(r[1]), "=r"(r[2]), "=r"(r[3]) : "r"(addr));
}
__device__ __forceinline__ void cp_async16(unsigned dst, const void* src) {
    asm volatile("cp.async.cg.shared.global [%0], [%1], 16;" :: "r"(dst), "l"(src));
}
__device__ __forceinline__ void cp_commit() {
    asm volatile("cp.async.commit_group;" ::: "memory");
}
template <int N>
__device__ __forceinline__ void cp_wait() {
    asm volatile("cp.async.wait_group %0;" :: "n"(N) : "memory");
}

// warp-level mean/invstd of 128 values held as 4x float4 per lane
__device__ __forceinline__ void row_stats(const float4* v, float& mean, float& r) {
    float s = 0.f, ss = 0.f;
    #pragma unroll
    for (int i = 0; i < 4; i++) {
        s  += v[i].x + v[i].y + v[i].z + v[i].w;
        ss += v[i].x * v[i].x + v[i].y * v[i].y + v[i].z * v[i].z + v[i].w * v[i].w;
    }
    #pragma unroll
    for (int o = 16; o > 0; o >>= 1) {
        s  += __shfl_xor_sync(0xffffffffu, s,  o);
        ss += __shfl_xor_sync(0xffffffffu, ss, o);
    }
    mean = s * (1.0f / D_MODEL);
    float var = (ss - (float)D_MODEL * mean * mean) * (1.0f / (D_MODEL - 1));
    var = fmaxf(var, 0.0f);
    r = 1.0f / (sqrtf(var) + EPS);
}

// ---------------- norm kernels (warp-per-row, 8 rows/CTA) ----------------------
__global__ __launch_bounds__(256)
void norm_first_kernel(const float* __restrict__ ext_in,
                       const float* __restrict__ alpha,
                       const float* __restrict__ beta)
{
    int tid = threadIdx.x, lane = tid & 31, wrp = tid >> 5;
    size_t row = (size_t)blockIdx.x * 8 + wrp;
    const float4* rp = (const float4*)(ext_in + row * D_MODEL);
    float4 v[4];
    #pragma unroll
    for (int i = 0; i < 4; i++) v[i] = rp[lane + 32 * i];
    float mean, r;
    row_stats(v, mean, r);
    #pragma unroll
    for (int i = 0; i < 4; i++) {
        int c4 = lane + 32 * i;
        float4 a4 = ((const float4*)alpha)[c4];
        float4 b4 = ((const float4*)beta)[c4];
        __half h0, h1, h2, h3, l0, l1, l2, l3;
        hsplit(a4.x * (v[i].x - mean) * r + b4.x, h0, l0);
        hsplit(a4.y * (v[i].y - mean) * r + b4.y, h1, l1);
        hsplit(a4.z * (v[i].z - mean) * r + b4.z, h2, l2);
        hsplit(a4.w * (v[i].w - mean) * r + b4.w, h3, l3);
        ((uint2*)(g_yh + row * D_MODEL))[c4] = hpack4(h0, h1, h2, h3);
        ((uint2*)(g_yl + row * D_MODEL))[c4] = hpack4(l0, l1, l2, l3);
    }
}

__global__ __launch_bounds__(256)
void norm_fused_kernel(const float* __restrict__ a2, const float* __restrict__ b2,
                       const float* __restrict__ a1, const float* __restrict__ b1)
{
    int tid = threadIdx.x, lane = tid & 31, wrp = tid >> 5;
    size_t row = (size_t)blockIdx.x * 8 + wrp;
    const float4* rp = (const float4*)(g_x + row * D_MODEL);
    float4 v[4];
    #pragma unroll
    for (int i = 0; i < 4; i++) v[i] = rp[lane + 32 * i];
    float mean, r;
    row_stats(v, mean, r);
    #pragma unroll
    for (int i = 0; i < 4; i++) {
        int c4 = lane + 32 * i;
        float4 a4 = ((const float4*)a2)[c4];
        float4 b4 = ((const float4*)b2)[c4];
        v[i].x = a4.x * (v[i].x - mean) * r + b4.x;
        v[i].y = a4.y * (v[i].y - mean) * r + b4.y;
        v[i].z = a4.z * (v[i].z - mean) * r + b4.z;
        v[i].w = a4.w * (v[i].w - mean) * r + b4.w;
    }
    row_stats(v, mean, r);
    #pragma unroll
    for (int i = 0; i < 4; i++) {
        int c4 = lane + 32 * i;
        float4 a4 = ((const float4*)a1)[c4];
        float4 b4 = ((const float4*)b1)[c4];
        __half h0, h1, h2, h3, l0, l1, l2, l3;
        hsplit(a4.x * (v[i].x - mean) * r + b4.x, h0, l0);
        hsplit(a4.y * (v[i].y - mean) * r + b4.y, h1, l1);
        hsplit(a4.z * (v[i].z - mean) * r + b4.z, h2, l2);
        hsplit(a4.w * (v[i].w - mean) * r + b4.w, h3, l3);
        ((uint2*)(g_yh + row * D_MODEL))[c4] = hpack4(h0, h1, h2, h3);
        ((uint2*)(g_yl + row * D_MODEL))[c4] = hpack4(l0, l1, l2, l3);
    }
}

__global__ __launch_bounds__(256)
void norm_last_kernel(const float* __restrict__ alpha,
                      const float* __restrict__ beta,
                      float* __restrict__ out)
{
    int tid = threadIdx.x, lane = tid & 31, wrp = tid >> 5;
    size_t row = (size_t)blockIdx.x * 8 + wrp;
    const float4* rp = (const float4*)(g_x + row * D_MODEL);
    float4 v[4];
    #pragma unroll
    for (int i = 0; i < 4; i++) v[i] = rp[lane + 32 * i];
    float mean, r;
    row_stats(v, mean, r);
    #pragma unroll
    for (int i = 0; i < 4; i++) {
        int c4 = lane + 32 * i;
        float4 a4 = ((const float4*)alpha)[c4];
        float4 b4 = ((const float4*)beta)[c4];
        float4 o4;
        o4.x = a4.x * (v[i].x - mean) * r + b4.x;
        o4.y = a4.y * (v[i].y - mean) * r + b4.y;
        o4.z = a4.z * (v[i].z - mean) * r + b4.z;
        o4.w = a4.w * (v[i].w - mean) * r + b4.w;
        ((float4*)(out + row * D_MODEL))[c4] = o4;
    }
}

// ---------------- column sum of y over seq (exact: yh+yl) ----------------------
__global__ void colsum_kernel()
{
    int bx = blockIdx.x;
    int b  = bx >> 6;
    int rem = bx & 63;
    int cb = rem >> 5;
    int sc = rem & 31;
    int c  = cb * 256 + threadIdx.x;

    size_t base = ((size_t)b * SEQ + (size_t)sc * 128) * D_MODEL + c;
    float a0 = 0.f, a1 = 0.f;
    #pragma unroll 8
    for (int s = 0; s < 128; s += 2) {
        size_t i0 = base + (size_t)(s + 0) * D_MODEL;
        size_t i1 = base + (size_t)(s + 1) * D_MODEL;
        a0 += __half2float(g_yh[i0]) + __half2float(g_yl[i0]);
        a1 += __half2float(g_yh[i1]) + __half2float(g_yl[i1]);
    }
    g_part[((size_t)b * SCHUNKS + sc) * D_MODEL + c] = a0 + a1;
}

__global__ void ksum_reduce_kernel()
{
    int idx = blockIdx.x * 256 + threadIdx.x;
    int b = idx >> 9;
    int c = idx & (D_MODEL - 1);
    float s = 0.f;
    #pragma unroll
    for (int k = 0; k < SCHUNKS; k++)
        s += g_part[((size_t)b * SCHUNKS + k) * D_MODEL + c];
    g_ksum[idx] = s;
}

// ---------------- scores: M = softmax + I ---------------------------------------
__global__ void scores_kernel(const float* __restrict__ convw,
                              const float* __restrict__ convb)
{
    __shared__ float ks[DK];
    int bh = blockIdx.x;
    int b = bh / HEADS, h = bh % HEADS;
    int c = threadIdx.x;
    ks[c] = g_ksum[b * D_MODEL + h * DK + c];
    __syncthreads();

    float w  = convw[c] * INV_SQRT_DK;
    float bb = (float)SEQ * convb[c] * INV_SQRT_DK;

    float logit[DK];
    float mx = -1e30f;
    #pragma unroll
    for (int j = 0; j < DK; j++) {
        logit[j] = fmaf(w, ks[j], bb);
        mx = fmaxf(mx, logit[j]);
    }
    float sum = 0.f;
    #pragma unroll
    for (int j = 0; j < DK; j++) {
        logit[j] = expf(logit[j] - mx);
        sum += logit[j];
    }
    float inv = 1.0f / sum;
    float* Mp = g_M + (size_t)bh * DK * DK;
    #pragma unroll
    for (int j = 0; j < DK; j++)
        Mp[j * DK + c] = logit[j] * inv + (j == c ? 1.0f : 0.0f);
}

// ---------------- W~ build: W~_b[o, h*64+j] = sum_c M_bh[j][c] * Wo[o, h*64+c] --
__global__ __launch_bounds__(256)
void make_wt_kernel(const float* __restrict__ Wo)
{
    __shared__ float Ms[DK][DK + 1];
    int bh = blockIdx.x;
    int b = bh >> 3, h = bh & 7;
    int tid = threadIdx.x;

    #pragma unroll
    for (int t = 0; t < 16; t++) {
        int lin = tid + 256 * t;
        Ms[lin >> 6][lin & 63] = g_M[(size_t)bh * DK * DK + lin];
    }
    __syncthreads();

    int j  = tid & 63;
    int og = tid >> 6;                 // 0..3
    #pragma unroll 1
    for (int ob = 0; ob < 8; ob++) {
        #pragma unroll 1
        for (int i = 0; i < 16; i++) {
            int o = ob * 64 + og * 16 + i;
            const float4* wrow = (const float4*)(Wo + (size_t)o * D_MODEL + h * DK);
            float s = 0.f;
            #pragma unroll
            for (int c4 = 0; c4 < 16; c4++) {
                float4 w4 = wrow[c4];
                s += w4.x * Ms[j][c4 * 4 + 0] + w4.y * Ms[j][c4 * 4 + 1]
                   + w4.z * Ms[j][c4 * 4 + 2] + w4.w * Ms[j][c4 * 4 + 3];
            }
            __half hh, hl;
            hsplit(s, hh, hl);
            size_t wi = ((size_t)b * D_MODEL + o) * D_MODEL + h * DK + j;
            g_Wth[wi] = hh;
            g_Wtl[wi] = hl;
        }
    }
}

// ---------------- WvT split (all layers, upfront): WvT[L][d][k] = Wv[L][k][d] ---
__global__ void convert_wvt_kernel(const float* __restrict__ Wv)
{
    size_t i = (size_t)blockIdx.x * 256 + threadIdx.x;   // output index
    size_t L = i / DD;
    size_t rem = i - L * DD;
    size_t d = rem >> 9;
    size_t k = rem & (D_MODEL - 1);
    float w = Wv[L * DD + k * D_MODEL + d];
    __half h, l;
    hsplit(w, h, l);
    g_WvTh[i] = h;
    g_WvTl[i] = l;
}

// ---------------- b^ : g_bhat[b][o] = bo[o] + sum_k W~_b[o,k] * bv[k] -----------
__global__ __launch_bounds__(512)
void bhat_kernel(const float* __restrict__ bo, const float* __restrict__ bv)
{
    __shared__ float bvs[D_MODEL];
    int b = blockIdx.x;
    int o = threadIdx.x;
    bvs[o] = bv[o];
    __syncthreads();

    const __half* wh = g_Wth + ((size_t)b * D_MODEL + o) * D_MODEL;
    const __half* wl = g_Wtl + ((size_t)b * D_MODEL + o) * D_MODEL;
    float s = 0.f;
    #pragma unroll 4
    for (int k = 0; k < D_MODEL; k++)
        s += (__half2float(wh[k]) + __half2float(wl[k])) * bvs[k];
    g_bhat[b * D_MODEL + o] = bo[o] + s;
}

// ---------------- 3-term HMMA GEMM engine (A,B both hi/lo split) ----------------
// MODE 0 (compose): C = W~ @ WvT^T  -> split to g_What/g_Whal.  grid (4, 64).
//   A rows (b,o) = g_Wth/g_Wtl; B rows d = g_WvTh/g_WvTl + layer.
// MODE 1 (big):    z = y + relu(y @ W^_b^T + b^_b) -> g_x.      grid (4, 512).
//   A rows = g_yh/g_yl; B rows o = g_What/g_Whal + batch (bm>>5).
#define BK 32
#define NCHK (D_MODEL / BK)      // 16
#define RSTRIDE 80
#define TILE_B (128 * RSTRIDE)   // 10240
#define G_T_AH 0u
#define G_T_AL ((unsigned)TILE_B)
#define G_T_BH ((unsigned)(2 * TILE_B))
#define G_T_BL ((unsigned)(3 * TILE_B))
#define G_STAGE (4 * TILE_B)
#define G_DYN (2 * G_STAGE)      // 81920

template <int MODE>
__global__ __launch_bounds__(256)
void gemm3_kernel(int layer)
{
    extern __shared__ __align__(16) char dyn[];
    const unsigned dynb = smem_u32(dyn);

    const int tid  = threadIdx.x;
    const int lane = tid & 31;
    const int wid  = tid >> 5;
    const int bn   = blockIdx.x;          // 0..3
    const int bm   = blockIdx.y;
    const int wm   = (wid & 3) * 32;
    const int wn   = (wid >> 2) * 64;

    const __half* Ah;
    const __half* Al;
    const __half* Bh;
    const __half* Bl;
    int batch = 0;
    if (MODE == 0) {
        Ah = g_Wth; Al = g_Wtl;
        Bh = g_WvTh + (size_t)layer * DD;
        Bl = g_WvTl + (size_t)layer * DD;
    } else {
        batch = bm >> 5;
        Ah = g_yh; Al = g_yl;
        Bh = g_What + (size_t)batch * DD;
        Bl = g_Whal + (size_t)batch * DD;
    }

    const size_t arow0 = (size_t)bm * 128;
    const size_t brow0 = (size_t)bn * 128;

    int ldRow[2], ldC[2];
    #pragma unroll
    for (int i = 0; i < 2; i++) {
        int lin = tid + i * 256;
        ldRow[i] = lin >> 2;
        ldC[i]   = lin & 3;
    }

    auto load_stage = [&](int chk, unsigned sb) {
        int k0 = chk * BK;
        #pragma unroll
        for (int i = 0; i < 2; i++) {
            unsigned so = (unsigned)(ldRow[i] * RSTRIDE + ldC[i] * 16);
            size_t ga = (arow0 + ldRow[i]) * D_MODEL + k0 + ldC[i] * 8;
            size_t gb = (brow0 + ldRow[i]) * D_MODEL + k0 + ldC[i] * 8;
            cp_async16(sb + G_T_AH + so, Ah + ga);
            cp_async16(sb + G_T_AL + so, Al + ga);
            cp_async16(sb + G_T_BH + so, Bh + gb);
            cp_async16(sb + G_T_BL + so, Bl + gb);
        }
    };

    float acc[2][8][4];
    #pragma unroll
    for (int im = 0; im < 2; im++)
        #pragma unroll
        for (int in = 0; in < 8; in++)
            #pragma unroll
            for (int q = 0; q < 4; q++) acc[im][in][q] = 0.f;

    load_stage(0, dynb);
    cp_commit();
    load_stage(1, dynb + G_STAGE);
    cp_commit();
    cp_wait<1>();
    __syncthreads();

    #pragma unroll 1
    for (int chk = 0; chk < NCHK; chk++) {
        const unsigned sb = dynb + (chk & 1) * G_STAGE;

        #pragma unroll
        for (int ks = 0; ks < 2; ks++) {
            unsigned ah[2][4], al[2][4];
            #pragma unroll
            for (int im = 0; im < 2; im++) {
                int row = wm + im * 16 + (lane & 15);
                unsigned cA = (unsigned)(ks * 2 + (lane >> 4));
                unsigned ad = (unsigned)(row * RSTRIDE) + cA * 16u;
                ldsm4(ah[im], sb + G_T_AH + ad);
                ldsm4(al[im], sb + G_T_AL + ad);
            }
            #pragma unroll
            for (int g = 0; g < 4; g++) {
                unsigned bh[4], bl[4];
                int row = wn + g * 16 + ((lane >> 4) * 8) + (lane & 7);
                unsigned cB = (unsigned)(ks * 2 + ((lane >> 3) & 1));
                unsigned bd = (unsigned)(row * RSTRIDE) + cB * 16u;
                ldsm4(bh, sb + G_T_BH + bd);
                ldsm4(bl, sb + G_T_BL + bd);
                #pragma unroll
                for (int im = 0; im < 2; im++) {
                    mma16816(acc[im][2 * g],     ah[im], &bh[0]);
                    mma16816(acc[im][2 * g],     ah[im], &bl[0]);
                    mma16816(acc[im][2 * g],     al[im], &bh[0]);
                    mma16816(acc[im][2 * g + 1], ah[im], &bh[2]);
                    mma16816(acc[im][2 * g + 1], ah[im], &bl[2]);
                    mma16816(acc[im][2 * g + 1], al[im], &bh[2]);
                }
            }
        }
        __syncthreads();
        if (chk + 2 < NCHK) {
            load_stage(chk + 2, sb);
            cp_commit();
            cp_wait<1>();
        } else {
            cp_wait<0>();
        }
        __syncthreads();
    }

    // ---------------- epilogue -------------------------------------------------
    #pragma unroll
    for (int im = 0; im < 2; im++) {
        int r0 = bm * 128 + wm + im * 16 + (lane >> 2);
        #pragma unroll
        for (int in = 0; in < 8; in++) {
            int col = bn * 128 + wn + in * 8 + (lane & 3) * 2;
            #pragma unroll
            for (int half = 0; half < 2; half++) {
                int row = r0 + half * 8;
                float v0 = acc[im][in][2 * half + 0];
                float v1 = acc[im][in][2 * half + 1];
                size_t gi = (size_t)row * D_MODEL + col;
                if (MODE == 0) {
                    __half h0, h1, l0, l1;
                    hsplit(v0, h0, l0);
                    hsplit(v1, h1, l1);
                    *(unsigned*)(g_What + gi) = hpack2(h0, h1);
                    *(unsigned*)(g_Whal + gi) = hpack2(l0, l1);
                } else {
                    float bb0 = g_bhat[batch * D_MODEL + col];
                    float bb1 = g_bhat[batch * D_MODEL + col + 1];
                    unsigned ryh = *(const unsigned*)(g_yh + gi);
                    unsigned ryl = *(const unsigned*)(g_yl + gi);
                    float2 yh = __half22float2(*(__half2*)&ryh);
                    float2 yl = __half22float2(*(__half2*)&ryl);
                    float o0 = (yh.x + yl.x) + fmaxf(v0 + bb0, 0.0f);
                    float o1 = (yh.y + yl.y) + fmaxf(v1 + bb1, 0.0f);
                    *(float2*)(g_x + gi) = make_float2(o0, o1);
                }
            }
        }
    }
}

// ---------------- driver ---------------------------------------------------------
extern "C" void kernel_launch(void* const* d_in, const int* in_sizes, int n_in,
                              void* d_out, int out_size)
{
    const float* x    = (const float*)d_in[0];
    const float* Wv   = (const float*)d_in[1];
    const float* bv   = (const float*)d_in[2];
    const float* cw   = (const float*)d_in[3];
    const float* cb   = (const float*)d_in[4];
    const float* Wo   = (const float*)d_in[5];
    const float* bo   = (const float*)d_in[6];
    const float* a1   = (const float*)d_in[7];
    const float* b1   = (const float*)d_in[8];
    const float* a2   = (const float*)d_in[9];
    const float* b2   = (const float*)d_in[10];
    float* out = (float*)d_out;

    cudaFuncSetAttribute(gemm3_kernel<0>, cudaFuncAttributeMaxDynamicSharedMemorySize, G_DYN);
    cudaFuncSetAttribute(gemm3_kernel<1>, cudaFuncAttributeMaxDynamicSharedMemorySize, G_DYN);

    // upfront: Wv transpose+split (all layers), first norm
    convert_wvt_kernel<<<(N_LAYERS * DD) / 256, 256>>>(Wv);
    norm_first_kernel<<<ROWS / 8, 256>>>(x, a1, b1);

    for (int L = 0; L < N_LAYERS; L++) {
        // ksum / scores / W~ / b^ / W^
        colsum_kernel<<<BS * 2 * SCHUNKS, 256>>>();
        ksum_reduce_kernel<<<32, 256>>>();
        scores_kernel<<<BS * HEADS, 64>>>(cw + L * DK, cb + L * DK);
        make_wt_kernel<<<BS * HEADS, 256>>>(Wo + (size_t)L * DD);
        bhat_kernel<<<BS, 512>>>(bo + L * D_MODEL, bv + L * D_MODEL);
        gemm3_kernel<0><<<dim3(4, 64), 256, G_DYN>>>(L);      // W^ = W~ @ Wv
        // z = y + relu(y @ W^^T + b^)   — the ONE big GEMM per layer
        gemm3_kernel<1><<<dim3(4, 512), 256, G_DYN>>>(L);
        // norms
        if (L < N_LAYERS - 1) {
            norm_fused_kernel<<<ROWS / 8, 256>>>(a2 + L * D_MODEL, b2 + L * D_MODEL,
                                                 a1 + (L + 1) * D_MODEL,
                                                 b1 + (L + 1) * D_MODEL);
        } else {
            norm_last_kernel<<<ROWS / 8, 256>>>(a2 + L * D_MODEL, b2 + L * D_MODEL, out);
        }
    }
}